// round 3
// baseline (speedup 1.0000x reference)
#include <cuda_runtime.h>
#include <cuda_bf16.h>

#define NN   4
#define CC   20
#define HH   64
#define WWID 2048
#define KHW  5

#define TILE 512          // output pixels per block (along W)
#define TPB  256          // threads per block; each thread owns 2 adjacent pixels
#define COLS (TILE + 4)   // 516 smem columns (tile + 4 halo)

// 0 = uint8 mask, 1 = int32 mask, 2 = float32 mask
__device__ int g_mask_mode;

__global__ void detect_mask_mode(const unsigned int* m)
{
    // Inspect first 64 words (256 bytes) — in-bounds for every candidate dtype
    // (smallest possible buffer is 524288 bytes for u8).
    bool all_i32 = true, all_f32 = true;
    for (int i = 0; i < 64; ++i) {
        unsigned int w = m[i];
        if (w != 0u && w != 1u)          all_i32 = false;
        if (w != 0u && w != 0x3F800000u) all_f32 = false;
    }
    g_mask_mode = all_i32 ? 1 : (all_f32 ? 2 : 0);
}

__global__ __launch_bounds__(TPB, 2)
void lcxyz_kernel(const float* __restrict__ xyz,
                  const float* __restrict__ softmax,
                  const void* __restrict__ mask,
                  float* __restrict__ out)
{
    __shared__ float msk_s[KHW][COLS];  // mask incl. OOB zeros, as float
    __shared__ float sm_s [KHW][COLS];  // masked softmax tile for current channel

    const int t  = threadIdx.x;
    const int w0 = blockIdx.x * TILE;
    const int h  = blockIdx.y;
    const int n  = blockIdx.z;
    const int mmode = g_mask_mode;

    // Clamped source rows for the 5 vertical taps (value irrelevant when masked 0)
    int hrow[KHW];
#pragma unroll
    for (int r = 0; r < KHW; ++r) {
        int hh = h + r - 2;
        hrow[r] = min(max(hh, 0), HH - 1);
    }

    // ---- Stage mask tile once (0 outside the image) ----
    {
        const size_t mbase = (size_t)n * HH * WWID;
        const unsigned char* mk_u8  = (const unsigned char*)mask + mbase;
        const int*           mk_i32 = (const int*)mask + mbase;
        const float*         mk_f32 = (const float*)mask + mbase;
#pragma unroll
        for (int r = 0; r < KHW; ++r) {
            int hh = h + r - 2;
            bool hok = (hh >= 0) && (hh < HH);
            for (int col = t; col < COLS; col += TPB) {
                int ww = w0 + col - 2;
                float v = 0.0f;
                if (hok && ww >= 0 && ww < WWID) {
                    size_t idx = (size_t)hh * WWID + ww;
                    if (mmode == 1)      v = (float)mk_i32[idx];
                    else if (mmode == 2) v = mk_f32[idx];
                    else                 v = (float)mk_u8[idx];
                }
                msk_s[r][col] = v;
            }
        }
    }

    // ---- Phase 1: per-thread Gaussian weights for 2 adjacent pixels ----
    const int wa = w0 + 2 * t;            // pixel 0 global w; pixel 1 = wa+1
    const size_t plane = (size_t)HH * WWID;
    const float* Xx = xyz + (size_t)n * 3 * plane;
    const float* Xy = Xx + plane;
    const float* Xz = Xy + plane;

    const float cx0 = Xx[h * WWID + wa];
    const float cy0 = Xy[h * WWID + wa];
    const float cz0 = Xz[h * WWID + wa];
    const float cx1 = Xx[h * WWID + wa + 1];
    const float cy1 = Xy[h * WWID + wa + 1];
    const float cz1 = Xz[h * WWID + wa + 1];

    float g0[25], g1[25];
#pragma unroll
    for (int dy = 0; dy < KHW; ++dy) {
        const int hc = hrow[dy];
        float nx[6], ny[6], nz[6];
#pragma unroll
        for (int j = 0; j < 6; ++j) {
            int ww = wa + j - 2;
            ww = min(max(ww, 0), WWID - 1);
            nx[j] = Xx[hc * WWID + ww];
            ny[j] = Xy[hc * WWID + ww];
            nz[j] = Xz[hc * WWID + ww];
        }
#pragma unroll
        for (int dx = 0; dx < KHW; ++dx) {
            float ax = nx[dx] - cx0, ay = ny[dx] - cy0, az = nz[dx] - cz0;
            float d2a = fmaf(ax, ax, fmaf(ay, ay, az * az));
            g0[dy * 5 + dx] = __expf(-0.5f * d2a);
            float bx = nx[dx + 1] - cx1, by = ny[dx + 1] - cy1, bz = nz[dx + 1] - cz1;
            float d2b = fmaf(bx, bx, fmaf(by, by, bz * bz));
            g1[dy * 5 + dx] = __expf(-0.5f * d2b);
        }
    }

    // ---- Phase 2: channel loop — stage masked sm tile, accumulate, store ----
    for (int c = 0; c < CC; ++c) {
        __syncthreads();   // protects sm_s from previous iteration's readers
                           // (and orders msk_s fill before first use)
        const float* smc = softmax + ((size_t)(n * CC + c)) * plane;
#pragma unroll
        for (int r = 0; r < KHW; ++r) {
            const float* srow = smc + hrow[r] * WWID;
            for (int col = t; col < COLS; col += TPB) {
                int ww = w0 + col - 2;
                int wc = min(max(ww, 0), WWID - 1);
                sm_s[r][col] = srow[wc] * msk_s[r][col];
            }
        }
        __syncthreads();

        float a0 = 0.0f, a1 = 0.0f;
#pragma unroll
        for (int dy = 0; dy < KHW; ++dy) {
            const float* rowp = &sm_s[dy][2 * t];     // 8B-aligned (2*t even, row pitch 2064B)
            float2 s01 = *(const float2*)(rowp);
            float2 s23 = *(const float2*)(rowp + 2);
            float2 s45 = *(const float2*)(rowp + 4);
            float s0 = s01.x, s1 = s01.y, s2 = s23.x, s3 = s23.y, s4 = s45.x, s5 = s45.y;
            a0 = fmaf(g0[dy * 5 + 0], s0, a0);  a1 = fmaf(g1[dy * 5 + 0], s1, a1);
            a0 = fmaf(g0[dy * 5 + 1], s1, a0);  a1 = fmaf(g1[dy * 5 + 1], s2, a1);
            a0 = fmaf(g0[dy * 5 + 2], s2, a0);  a1 = fmaf(g1[dy * 5 + 2], s3, a1);
            a0 = fmaf(g0[dy * 5 + 3], s3, a0);  a1 = fmaf(g1[dy * 5 + 3], s4, a1);
            a0 = fmaf(g0[dy * 5 + 4], s4, a0);  a1 = fmaf(g1[dy * 5 + 4], s5, a1);
        }

        float2* op = (float2*)(out + ((size_t)(n * CC + c) * HH + h) * WWID + wa);
        *op = make_float2(a0, a1);
    }
}

extern "C" void kernel_launch(void* const* d_in, const int* in_sizes, int n_in,
                              void* d_out, int out_size)
{
    const float* xyz     = (const float*)d_in[0];
    const float* softmax = (const float*)d_in[1];
    const void*  mask    = d_in[2];
    float*       out     = (float*)d_out;

    detect_mask_mode<<<1, 1>>>((const unsigned int*)mask);

    dim3 grid(WWID / TILE, HH, NN);   // (4, 64, 4) = 1024 blocks
    dim3 block(TPB);
    lcxyz_kernel<<<grid, block>>>(xyz, softmax, mask, out);
}

// round 4
// speedup vs baseline: 4.9023x; 4.9023x over previous
#include <cuda_runtime.h>

#define NN   4
#define CC   20
#define HH   64
#define WWID 2048
#define KHW  5

#define TPB  128
#define TILE 256          // output pixels per block; 2 px per thread
#define COLS 264          // staged cols: ww = w0-4 .. w0+259 ; col = ww - w0 + 4
#define NV4  (COLS / 4)   // 66 float4 per staged row
#define PLANE (HH * WWID) // 131072

// 0 = uint8 mask, 1 = int32 mask, 2 = float32 mask
__device__ int g_mask_mode;

__global__ void detect_mask_mode(const unsigned int* m)
{
    bool all_i32 = true, all_f32 = true;
    for (int i = 0; i < 64; ++i) {
        unsigned int w = m[i];
        if (w != 0u && w != 1u)          all_i32 = false;
        if (w != 0u && w != 0x3F800000u) all_f32 = false;
    }
    g_mask_mode = all_i32 ? 1 : (all_f32 ? 2 : 0);
}

__device__ __forceinline__ void cp_async16(void* smem, const void* gmem)
{
    unsigned saddr = (unsigned)__cvta_generic_to_shared(smem);
    asm volatile("cp.async.cg.shared.global [%0], [%1], 16;\n"
                 :: "r"(saddr), "l"(gmem));
}
__device__ __forceinline__ void cp_commit()
{
    asm volatile("cp.async.commit_group;\n" ::: "memory");
}
template <int N>
__device__ __forceinline__ void cp_wait()
{
    asm volatile("cp.async.wait_group %0;\n" :: "n"(N) : "memory");
}

__global__ __launch_bounds__(TPB, 5)
void lcxyz_kernel(const float* __restrict__ xyz,
                  const float* __restrict__ softmax,
                  const void* __restrict__ mask,
                  float* __restrict__ out)
{
    __shared__ float ph1[4][KHW][COLS];   // [mask, x, y, z] staged tiles (phase 1 only)
    __shared__ float sms[2][KHW][COLS];   // double-buffered softmax tile

    const int t  = threadIdx.x;
    const int w0 = blockIdx.x * TILE;
    const int h  = blockIdx.y;
    const int n  = blockIdx.z;
    const int mmode = g_mask_mode;

    int hrow[KHW];
#pragma unroll
    for (int r = 0; r < KHW; ++r)
        hrow[r] = min(max(h + r - 2, 0), HH - 1);

    const float* sm_base = softmax + (size_t)(n * CC) * PLANE;

    // ---- Prologue: prefetch channel 0 tile (address-clamped float4 cp.async) ----
    {
        const float* smc0 = sm_base;                    // c = 0
        for (int j = t; j < KHW * NV4; j += TPB) {
            int r = j / NV4, i = j % NV4;
            int gidx = hrow[r] * WWID + (w0 - 4) + 4 * i;
            gidx = min(max(gidx, 0), PLANE - 4);        // edge garbage killed by gm=0
            cp_async16(&sms[0][r][4 * i], smc0 + gidx);
        }
        cp_commit();
    }

    // ---- Stage mask tile (OOB -> 0) and xyz tiles (index-clamped) ----
    {
        const size_t mbase = (size_t)n * PLANE;
        const unsigned char* mk_u8  = (const unsigned char*)mask + mbase;
        const int*           mk_i32 = (const int*)mask + mbase;
        const float*         mk_f32 = (const float*)mask + mbase;

        for (int j = t; j < KHW * COLS; j += TPB) {
            int r = j / COLS, col = j % COLS;
            int hh = h + r - 2;
            int ww = w0 + col - 4;
            float v = 0.0f;
            if (hh >= 0 && hh < HH && ww >= 0 && ww < WWID) {
                int idx = hh * WWID + ww;
                if (mmode == 1)      v = (float)mk_i32[idx];
                else if (mmode == 2) v = mk_f32[idx];
                else                 v = (float)mk_u8[idx];
            }
            ph1[0][r][col] = v;
        }

        const float* Xp = xyz + (size_t)n * 3 * PLANE;
#pragma unroll
        for (int p = 0; p < 3; ++p) {
            const float* X = Xp + (size_t)p * PLANE;
            for (int j = t; j < KHW * COLS; j += TPB) {
                int r = j / COLS, col = j % COLS;
                int ww = min(max(w0 + col - 4, 0), WWID - 1);
                ph1[p + 1][r][col] = X[hrow[r] * WWID + ww];
            }
        }
    }
    __syncthreads();

    // ---- Phase 1: per-thread masked Gaussian weights for 2 adjacent pixels ----
    const int wa = w0 + 2 * t;         // pixel 0; pixel 1 = wa+1
    const int cc = 2 * t + 4;          // staged col of wa

    const float cx0 = ph1[1][2][cc],     cy0 = ph1[2][2][cc],     cz0 = ph1[3][2][cc];
    const float cx1 = ph1[1][2][cc + 1], cy1 = ph1[2][2][cc + 1], cz1 = ph1[3][2][cc + 1];

    float gm0[25], gm1[25];
#pragma unroll
    for (int dy = 0; dy < KHW; ++dy) {
        // window cols cc-2 .. cc+3 (even start -> aligned float2)
        float m[6], nx[6], ny[6], nz[6];
#pragma unroll
        for (int j = 0; j < 3; ++j) {
            float2 mv = *(const float2*)&ph1[0][dy][cc - 2 + 2 * j];
            float2 xv = *(const float2*)&ph1[1][dy][cc - 2 + 2 * j];
            float2 yv = *(const float2*)&ph1[2][dy][cc - 2 + 2 * j];
            float2 zv = *(const float2*)&ph1[3][dy][cc - 2 + 2 * j];
            m[2*j] = mv.x;  m[2*j+1] = mv.y;
            nx[2*j] = xv.x; nx[2*j+1] = xv.y;
            ny[2*j] = yv.x; ny[2*j+1] = yv.y;
            nz[2*j] = zv.x; nz[2*j+1] = zv.y;
        }
#pragma unroll
        for (int dx = 0; dx < KHW; ++dx) {
            float ax = nx[dx] - cx0, ay = ny[dx] - cy0, az = nz[dx] - cz0;
            float d2a = fmaf(ax, ax, fmaf(ay, ay, az * az));
            gm0[dy * 5 + dx] = m[dx] * __expf(-0.5f * d2a);
            float bx = nx[dx+1] - cx1, by = ny[dx+1] - cy1, bz = nz[dx+1] - cz1;
            float d2b = fmaf(bx, bx, fmaf(by, by, bz * bz));
            gm1[dy * 5 + dx] = m[dx + 1] * __expf(-0.5f * d2b);
        }
    }

    // ---- Phase 2: channel loop, double-buffered cp.async pipeline ----
    for (int c = 0; c < CC; ++c) {
        if (c + 1 < CC) {
            const float* smcn = sm_base + (size_t)(c + 1) * PLANE;
            float* buf = &sms[(c + 1) & 1][0][0];
            for (int j = t; j < KHW * NV4; j += TPB) {
                int r = j / NV4, i = j % NV4;
                int gidx = hrow[r] * WWID + (w0 - 4) + 4 * i;
                gidx = min(max(gidx, 0), PLANE - 4);
                cp_async16(buf + r * COLS + 4 * i, smcn + gidx);
            }
            cp_commit();
            cp_wait<1>();      // current channel's group done; next may be in flight
        } else {
            cp_wait<0>();
        }
        __syncthreads();

        const float (*B)[COLS] = sms[c & 1];
        float a0 = 0.0f, a1 = 0.0f;
#pragma unroll
        for (int dy = 0; dy < KHW; ++dy) {
            const float* rowp = &B[dy][cc - 2];          // even index -> aligned
            float2 s01 = *(const float2*)(rowp);
            float2 s23 = *(const float2*)(rowp + 2);
            float2 s45 = *(const float2*)(rowp + 4);
            float s0 = s01.x, s1 = s01.y, s2 = s23.x, s3 = s23.y, s4 = s45.x, s5 = s45.y;
            a0 = fmaf(gm0[dy*5+0], s0, a0);  a1 = fmaf(gm1[dy*5+0], s1, a1);
            a0 = fmaf(gm0[dy*5+1], s1, a0);  a1 = fmaf(gm1[dy*5+1], s2, a1);
            a0 = fmaf(gm0[dy*5+2], s2, a0);  a1 = fmaf(gm1[dy*5+2], s3, a1);
            a0 = fmaf(gm0[dy*5+3], s3, a0);  a1 = fmaf(gm1[dy*5+3], s4, a1);
            a0 = fmaf(gm0[dy*5+4], s4, a0);  a1 = fmaf(gm1[dy*5+4], s5, a1);
        }

        float2* op = (float2*)(out + ((size_t)(n * CC + c) * HH + h) * WWID + wa);
        *op = make_float2(a0, a1);

        __syncthreads();   // all readers done before buf[c&1] is refilled at iter c+1
    }
}

extern "C" void kernel_launch(void* const* d_in, const int* in_sizes, int n_in,
                              void* d_out, int out_size)
{
    const float* xyz     = (const float*)d_in[0];
    const float* softmax = (const float*)d_in[1];
    const void*  mask    = d_in[2];
    float*       out     = (float*)d_out;

    detect_mask_mode<<<1, 1>>>((const unsigned int*)mask);

    dim3 grid(WWID / TILE, HH, NN);   // (8, 64, 4) = 2048 blocks
    dim3 block(TPB);
    lcxyz_kernel<<<grid, block>>>(xyz, softmax, mask, out);
}

// round 6
// speedup vs baseline: 5.2876x; 1.0786x over previous
#include <cuda_runtime.h>

#define NN    4
#define CC    20
#define HH    64
#define WWID  2048
#define KHW   5
#define PLANE (HH * WWID)     // 131072

#define TPB   128
#define TILE  256             // output px per block, 2 px/thread
#define COLS  264             // staged cols: ww = w0-4 .. w0+259
#define NV4   (COLS / 4)      // 66 float4 per row
#define CH_PER_G   2
#define NGROUPS    (CC / CH_PER_G)           // 10
#define GBUF_FLTS  (CH_PER_G * KHW * COLS)   // 2640 floats per group buffer
#define SLOTS      (CH_PER_G * KHW * NV4)    // 660 float4 copies per group
#define SLOTS_PT   ((SLOTS + TPB - 1) / TPB) // 6 per thread

__device__ __forceinline__ void cp_async16(void* smem, const void* gmem)
{
    unsigned saddr = (unsigned)__cvta_generic_to_shared(smem);
    asm volatile("cp.async.cg.shared.global [%0], [%1], 16;\n"
                 :: "r"(saddr), "l"(gmem));
}
__device__ __forceinline__ void cp_commit()
{
    asm volatile("cp.async.commit_group;\n" ::: "memory");
}
template <int N>
__device__ __forceinline__ void cp_wait()
{
    asm volatile("cp.async.wait_group %0;\n" :: "n"(N) : "memory");
}

__global__ __launch_bounds__(TPB, 5)
void lcxyz_kernel(const float* __restrict__ xyz,
                  const float* __restrict__ softmax,
                  const void* __restrict__ mask,
                  float* __restrict__ out)
{
    __shared__ float S[2 * GBUF_FLTS];        // double-buffered softmax groups (21120 B)
    __shared__ float ph1f[4 * KHW * COLS];    // phase-1 scratch: mask,x,y,z (21120 B)
    __shared__ int   sh_mode;

    float* const GB0 = S;
    float* const GB1 = S + GBUF_FLTS;

    const int t  = threadIdx.x;
    const int w0 = blockIdx.x * TILE;
    const int h  = blockIdx.y;
    const int n  = blockIdx.z;

    // ---- mask dtype detection (warp 0): 0=u8, 1=i32, 2=f32 ----
    if (t < 32) {
        const unsigned* m = (const unsigned*)mask;
        unsigned w1 = m[t], w2 = m[t + 32];
        bool i32ok = (w1 <= 1u) && (w2 <= 1u);
        bool f32ok = (w1 == 0u || w1 == 0x3F800000u) &&
                     (w2 == 0u || w2 == 0x3F800000u);
        unsigned bi = __ballot_sync(0xFFFFFFFFu, i32ok);
        unsigned bf = __ballot_sync(0xFFFFFFFFu, f32ok);
        if (t == 0) sh_mode = (bi == 0xFFFFFFFFu) ? 1 : ((bf == 0xFFFFFFFFu) ? 2 : 0);
    }

    int hrow[KHW];
#pragma unroll
    for (int r = 0; r < KHW; ++r)
        hrow[r] = min(max(h + r - 2, 0), HH - 1);

    const float* sm_base = softmax + (size_t)(n * CC) * PLANE;

    // ---- Precompute staging slots (once; reused for all 10 groups) ----
    unsigned soff[SLOTS_PT];   // float index into group buffer
    unsigned goff[SLOTS_PT];   // float index into 2-channel gmem chunk
    bool     sval[SLOTS_PT];
#pragma unroll
    for (int k = 0; k < SLOTS_PT; ++k) {
        int j = t + TPB * k;
        sval[k] = (j < SLOTS);
        int jj = sval[k] ? j : 0;
        int ch  = jj / (KHW * NV4);
        int rem = jj - ch * (KHW * NV4);
        int rr  = rem / NV4;
        int i   = rem - rr * NV4;
        soff[k] = ch * (KHW * COLS) + rr * COLS + 4 * i;
        int gidx = hrow[rr] * WWID + (w0 - 4) + 4 * i;
        gidx = min(max(gidx, 0), PLANE - 4);     // edge garbage killed by gm=0
        goff[k] = ch * PLANE + gidx;
    }

    // ---- Prologue: prefetch group 0 into GB0 (overlaps phase-1 work) ----
#pragma unroll
    for (int k = 0; k < SLOTS_PT; ++k)
        if (sval[k]) cp_async16(GB0 + soff[k], sm_base + goff[k]);
    cp_commit();

    __syncthreads();    // sh_mode visible before mask staging

    // ---- Stage phase-1 tiles: mask (OOB->0) + xyz (clamped) ----
    {
        const int mmode = sh_mode;
        const size_t mbase = (size_t)n * PLANE;
        const unsigned char* mk_u8  = (const unsigned char*)mask + mbase;
        const int*           mk_i32 = (const int*)mask + mbase;
        const float*         mk_f32 = (const float*)mask + mbase;

        for (int j = t; j < KHW * COLS; j += TPB) {
            int r = j / COLS, col = j - r * COLS;
            int hh = h + r - 2;
            int ww = w0 + col - 4;
            float v = 0.0f;
            if (hh >= 0 && hh < HH && ww >= 0 && ww < WWID) {
                int idx = hh * WWID + ww;
                if (mmode == 1)      v = (float)mk_i32[idx];
                else if (mmode == 2) v = mk_f32[idx];
                else                 v = (float)mk_u8[idx];
            }
            ph1f[j] = v;     // plane 0 = mask
        }
        const float* Xp = xyz + (size_t)n * 3 * PLANE;
#pragma unroll
        for (int p = 0; p < 3; ++p) {
            const float* X = Xp + (size_t)p * PLANE;
            for (int j = t; j < KHW * COLS; j += TPB) {
                int r = j / COLS, col = j - r * COLS;
                int ww = min(max(w0 + col - 4, 0), WWID - 1);
                ph1f[(p + 1) * (KHW * COLS) + j] = X[hrow[r] * WWID + ww];
            }
        }
    }
    __syncthreads();

    // ---- Phase 1: masked Gaussian weights for 2 adjacent pixels ----
    const int wa = w0 + 2 * t;
    const int cc = 2 * t + 4;

    const float cx0 = ph1f[1*(KHW*COLS) + 2*COLS + cc];
    const float cy0 = ph1f[2*(KHW*COLS) + 2*COLS + cc];
    const float cz0 = ph1f[3*(KHW*COLS) + 2*COLS + cc];
    const float cx1 = ph1f[1*(KHW*COLS) + 2*COLS + cc + 1];
    const float cy1 = ph1f[2*(KHW*COLS) + 2*COLS + cc + 1];
    const float cz1 = ph1f[3*(KHW*COLS) + 2*COLS + cc + 1];

    float gm0[25], gm1[25];
#pragma unroll
    for (int dy = 0; dy < KHW; ++dy) {
        float m[6], nx[6], ny[6], nz[6];
#pragma unroll
        for (int j = 0; j < 3; ++j) {
            float2 mv = *(const float2*)&ph1f[0*(KHW*COLS) + dy*COLS + cc - 2 + 2*j];
            float2 xv = *(const float2*)&ph1f[1*(KHW*COLS) + dy*COLS + cc - 2 + 2*j];
            float2 yv = *(const float2*)&ph1f[2*(KHW*COLS) + dy*COLS + cc - 2 + 2*j];
            float2 zv = *(const float2*)&ph1f[3*(KHW*COLS) + dy*COLS + cc - 2 + 2*j];
            m [2*j] = mv.x;  m [2*j+1] = mv.y;
            nx[2*j] = xv.x;  nx[2*j+1] = xv.y;
            ny[2*j] = yv.x;  ny[2*j+1] = yv.y;
            nz[2*j] = zv.x;  nz[2*j+1] = zv.y;
        }
#pragma unroll
        for (int dx = 0; dx < KHW; ++dx) {
            float ax = nx[dx] - cx0, ay = ny[dx] - cy0, az = nz[dx] - cz0;
            float d2a = fmaf(ax, ax, fmaf(ay, ay, az * az));
            gm0[dy*5+dx] = m[dx] * __expf(-0.5f * d2a);
            float bx = nx[dx+1] - cx1, by = ny[dx+1] - cy1, bz = nz[dx+1] - cz1;
            float d2b = fmaf(bx, bx, fmaf(by, by, bz * bz));
            gm1[dy*5+dx] = m[dx+1] * __expf(-0.5f * d2b);
        }
    }

    // ---- Phase 2: 10 groups of 2 channels, double-buffered ----
    float* outp = out + ((size_t)(n * CC) * HH + h) * WWID + wa;

    for (int g = 0; g < NGROUPS; ++g) {
        if (g + 1 < NGROUPS) {
            const float* gb = sm_base + (size_t)(g + 1) * (CH_PER_G * PLANE);
            float* buf = ((g + 1) & 1) ? GB1 : GB0;
#pragma unroll
            for (int k = 0; k < SLOTS_PT; ++k)
                if (sval[k]) cp_async16(buf + soff[k], gb + goff[k]);
            cp_commit();
            cp_wait<1>();      // group g complete; group g+1 may remain in flight
        } else {
            cp_wait<0>();
        }
        __syncthreads();

        const float* B = (g & 1) ? GB1 : GB0;
#pragma unroll
        for (int ch = 0; ch < CH_PER_G; ++ch) {
            const float* Bc = B + ch * (KHW * COLS);
            float a0 = 0.0f, a1 = 0.0f;
#pragma unroll
            for (int dy = 0; dy < KHW; ++dy) {
                const float* rowp = Bc + dy * COLS + (cc - 2);   // even -> 8B aligned
                float2 s01 = *(const float2*)(rowp);
                float2 s23 = *(const float2*)(rowp + 2);
                float2 s45 = *(const float2*)(rowp + 4);
                float s0 = s01.x, s1 = s01.y, s2 = s23.x,
                      s3 = s23.y, s4 = s45.x, s5 = s45.y;
                a0 = fmaf(gm0[dy*5+0], s0, a0);  a1 = fmaf(gm1[dy*5+0], s1, a1);
                a0 = fmaf(gm0[dy*5+1], s1, a0);  a1 = fmaf(gm1[dy*5+1], s2, a1);
                a0 = fmaf(gm0[dy*5+2], s2, a0);  a1 = fmaf(gm1[dy*5+2], s3, a1);
                a0 = fmaf(gm0[dy*5+3], s3, a0);  a1 = fmaf(gm1[dy*5+3], s4, a1);
                a0 = fmaf(gm0[dy*5+4], s4, a0);  a1 = fmaf(gm1[dy*5+4], s5, a1);
            }
            *(float2*)(outp + (size_t)(g * CH_PER_G + ch) * PLANE) = make_float2(a0, a1);
        }
        __syncthreads();   // readers of B done before it is refilled next iter
    }
}

extern "C" void kernel_launch(void* const* d_in, const int* in_sizes, int n_in,
                              void* d_out, int out_size)
{
    const float* xyz     = (const float*)d_in[0];
    const float* softmax = (const float*)d_in[1];
    const void*  mask    = d_in[2];
    float*       out     = (float*)d_out;

    dim3 grid(WWID / TILE, HH, NN);   // (8, 64, 4) = 2048 blocks
    dim3 block(TPB);
    lcxyz_kernel<<<grid, block>>>(xyz, softmax, mask, out);
}

// round 7
// speedup vs baseline: 5.8737x; 1.1108x over previous
#include <cuda_runtime.h>

#define NN    4
#define CC    20
#define HH    64
#define WWID  2048
#define KHW   5
#define PLANE (HH * WWID)     // 131072

#define TPB   128
#define TILE  256             // output px per block, 2 px/thread
#define COLS  264             // staged cols: ww = w0-4 .. w0+259
#define NV4   (COLS / 4)      // 66 float4 per row
#define CH_PER_G   2
#define NGROUPS    (CC / CH_PER_G)           // 10
#define STAGE_FLTS (CH_PER_G * KHW * COLS)   // 2640 floats per ring stage
#define NSTAGE     4                          // ring depth (42240 B total)
#define SLOTS      (CH_PER_G * KHW * NV4)    // 660 float4 copies per group
#define SLOTS_PT   ((SLOTS + TPB - 1) / TPB) // 6 per thread

__device__ __forceinline__ void cp_async16(void* smem, const void* gmem)
{
    unsigned saddr = (unsigned)__cvta_generic_to_shared(smem);
    asm volatile("cp.async.cg.shared.global [%0], [%1], 16;\n"
                 :: "r"(saddr), "l"(gmem));
}
__device__ __forceinline__ void cp_commit()
{
    asm volatile("cp.async.commit_group;\n" ::: "memory");
}
template <int N>
__device__ __forceinline__ void cp_wait()
{
    asm volatile("cp.async.wait_group %0;\n" :: "n"(N) : "memory");
}

__global__ __launch_bounds__(TPB, 5)
void lcxyz_kernel(const float* __restrict__ xyz,
                  const float* __restrict__ softmax,
                  const void* __restrict__ mask,
                  float* __restrict__ out)
{
    __shared__ float ring[NSTAGE * STAGE_FLTS];   // 42240 B: whole budget = pipeline
    __shared__ int   sh_mode;

    const int t  = threadIdx.x;
    const int w0 = blockIdx.x * TILE;
    const int h  = blockIdx.y;
    const int n  = blockIdx.z;

    // ---- mask dtype detection (warp 0): 0=u8, 1=i32, 2=f32 ----
    if (t < 32) {
        const unsigned* m = (const unsigned*)mask;
        unsigned w1 = m[t], w2 = m[t + 32];
        bool i32ok = (w1 <= 1u) && (w2 <= 1u);
        bool f32ok = (w1 == 0u || w1 == 0x3F800000u) &&
                     (w2 == 0u || w2 == 0x3F800000u);
        unsigned bi = __ballot_sync(0xFFFFFFFFu, i32ok);
        unsigned bf = __ballot_sync(0xFFFFFFFFu, f32ok);
        if (t == 0) sh_mode = (bi == 0xFFFFFFFFu) ? 1 : ((bf == 0xFFFFFFFFu) ? 2 : 0);
    }

    int hrow[KHW];
#pragma unroll
    for (int r = 0; r < KHW; ++r)
        hrow[r] = min(max(h + r - 2, 0), HH - 1);

    const float* sm_base = softmax + (size_t)(n * CC) * PLANE;

    // ---- Precompute staging slots (reused for all groups) ----
    unsigned soff[SLOTS_PT];   // float index into a ring stage
    unsigned goff[SLOTS_PT];   // float index into 2-channel gmem chunk
    bool     sval[SLOTS_PT];
#pragma unroll
    for (int k = 0; k < SLOTS_PT; ++k) {
        int j = t + TPB * k;
        sval[k] = (j < SLOTS);
        int jj = sval[k] ? j : 0;
        int ch  = jj / (KHW * NV4);
        int rem = jj - ch * (KHW * NV4);
        int rr  = rem / NV4;
        int i   = rem - rr * NV4;
        soff[k] = ch * (KHW * COLS) + rr * COLS + 4 * i;
        int gidx = hrow[rr] * WWID + (w0 - 4) + 4 * i;
        gidx = min(max(gidx, 0), PLANE - 4);     // edge garbage killed by gm=0
        goff[k] = ch * PLANE + gidx;
    }

    // ---- Prologue: prefetch groups 0 and 1 (hidden under phase-1 compute) ----
#pragma unroll
    for (int k = 0; k < SLOTS_PT; ++k)
        if (sval[k]) cp_async16(ring + soff[k], sm_base + goff[k]);
    cp_commit();
#pragma unroll
    for (int k = 0; k < SLOTS_PT; ++k)
        if (sval[k]) cp_async16(ring + STAGE_FLTS + soff[k],
                                sm_base + CH_PER_G * PLANE + goff[k]);
    cp_commit();

    __syncthreads();    // sh_mode visible
    const int mmode = sh_mode;

    // ---- Phase 1: masked Gaussian weights for 2 adjacent pixels (direct gmem) ----
    const int wa = w0 + 2 * t;
    const int cc = 2 * t + 4;                    // ring col of wa

    const float* Xx = xyz + (size_t)n * 3 * PLANE;
    const float* Xy = Xx + PLANE;
    const float* Xz = Xy + PLANE;
    const size_t mbase = (size_t)n * PLANE;
    const unsigned char* mk_u8  = (const unsigned char*)mask + mbase;
    const int*           mk_i32 = (const int*)mask + mbase;
    const float*         mk_f32 = (const float*)mask + mbase;

    const float cx0 = Xx[h * WWID + wa],     cy0 = Xy[h * WWID + wa],     cz0 = Xz[h * WWID + wa];
    const float cx1 = Xx[h * WWID + wa + 1], cy1 = Xy[h * WWID + wa + 1], cz1 = Xz[h * WWID + wa + 1];

    float gm0[25], gm1[25];
#pragma unroll
    for (int dy = 0; dy < KHW; ++dy) {
        const int hc  = hrow[dy];
        const int hh  = h + dy - 2;
        const bool hok = (hh >= 0) && (hh < HH);
        float m[6], nx[6], ny[6], nz[6];
#pragma unroll
        for (int j = 0; j < 6; ++j) {
            int wraw = wa + j - 2;
            int ww = min(max(wraw, 0), WWID - 1);
            int idx = hc * WWID + ww;
            nx[j] = Xx[idx];  ny[j] = Xy[idx];  nz[j] = Xz[idx];
            bool ok = hok && (wraw >= 0) && (wraw < WWID);
            float mv = 0.0f;
            if (ok) {
                if (mmode == 1)      mv = (float)mk_i32[idx];
                else if (mmode == 2) mv = mk_f32[idx];
                else                 mv = (float)mk_u8[idx];
            }
            m[j] = mv;
        }
#pragma unroll
        for (int dx = 0; dx < KHW; ++dx) {
            float ax = nx[dx] - cx0, ay = ny[dx] - cy0, az = nz[dx] - cz0;
            float d2a = fmaf(ax, ax, fmaf(ay, ay, az * az));
            gm0[dy*5+dx] = m[dx] * __expf(-0.5f * d2a);
            float bx = nx[dx+1] - cx1, by = ny[dx+1] - cy1, bz = nz[dx+1] - cz1;
            float d2b = fmaf(bx, bx, fmaf(by, by, bz * bz));
            gm1[dy*5+dx] = m[dx+1] * __expf(-0.5f * d2b);
        }
    }

    // ---- Phase 2: 10 groups, 4-stage ring, prefetch distance 2, 1 barrier/group ----
    float* outp = out + ((size_t)(n * CC) * HH + h) * WWID + wa;

    for (int g = 0; g < NGROUPS; ++g) {
        if (g + 2 < NGROUPS) {
            const float* gb = sm_base + (size_t)(g + 2) * (CH_PER_G * PLANE);
            float* buf = ring + ((g + 2) & (NSTAGE - 1)) * STAGE_FLTS;
#pragma unroll
            for (int k = 0; k < SLOTS_PT; ++k)
                if (sval[k]) cp_async16(buf + soff[k], gb + goff[k]);
            cp_commit();
            cp_wait<2>();       // group g complete; g+1, g+2 may be in flight
        } else if (g + 1 < NGROUPS) {
            cp_wait<1>();
        } else {
            cp_wait<0>();
        }
        __syncthreads();        // staged data visible; also fences stage reuse

        const float* B = ring + (g & (NSTAGE - 1)) * STAGE_FLTS;
#pragma unroll
        for (int ch = 0; ch < CH_PER_G; ++ch) {
            const float* Bc = B + ch * (KHW * COLS);
            float a0 = 0.0f, a1 = 0.0f;
#pragma unroll
            for (int dy = 0; dy < KHW; ++dy) {
                const float* rowp = Bc + dy * COLS + (cc - 2);   // even -> 8B aligned
                float2 s01 = *(const float2*)(rowp);
                float2 s23 = *(const float2*)(rowp + 2);
                float2 s45 = *(const float2*)(rowp + 4);
                float s0 = s01.x, s1 = s01.y, s2 = s23.x,
                      s3 = s23.y, s4 = s45.x, s5 = s45.y;
                a0 = fmaf(gm0[dy*5+0], s0, a0);  a1 = fmaf(gm1[dy*5+0], s1, a1);
                a0 = fmaf(gm0[dy*5+1], s1, a0);  a1 = fmaf(gm1[dy*5+1], s2, a1);
                a0 = fmaf(gm0[dy*5+2], s2, a0);  a1 = fmaf(gm1[dy*5+2], s3, a1);
                a0 = fmaf(gm0[dy*5+3], s3, a0);  a1 = fmaf(gm1[dy*5+3], s4, a1);
                a0 = fmaf(gm0[dy*5+4], s4, a0);  a1 = fmaf(gm1[dy*5+4], s5, a1);
            }
            *(float2*)(outp + (size_t)(g * CH_PER_G + ch) * PLANE) = make_float2(a0, a1);
        }
        // no second barrier: stage (g+2)%4 written at iter g was last read at
        // iter g-2; the iter g-1 and iter g barriers separate read from write.
    }
}

extern "C" void kernel_launch(void* const* d_in, const int* in_sizes, int n_in,
                              void* d_out, int out_size)
{
    const float* xyz     = (const float*)d_in[0];
    const float* softmax = (const float*)d_in[1];
    const void*  mask    = d_in[2];
    float*       out     = (float*)d_out;

    dim3 grid(WWID / TILE, HH, NN);   // (8, 64, 4) = 2048 blocks
    dim3 block(TPB);
    lcxyz_kernel<<<grid, block>>>(xyz, softmax, mask, out);
}